// round 5
// baseline (speedup 1.0000x reference)
#include <cuda_runtime.h>
#include <math.h>

// Problem constants (fixed shapes from setup_inputs)
#define BATCH 2
#define NPT   4096      // N = H*W
#define CH    128       // feature channels
#define TK    8         // top-k
#define NP1   4097
#define HH    64
#define WW    64
#define FULLMASK 0xffffffffu

// ---------------- device scratch (static allocation only) ----------------
__device__ float  g_invA[BATCH * NPT];
__device__ float  g_invB[BATCH * NPT];
__device__ float  g_E[(size_t)BATCH * NPT * NPT];      // exp(scores), 134 MB
__device__ float  g_eu[BATCH * NP1];
__device__ float  g_ev[BATCH * NP1];
__device__ float  g_colsum[BATCH * NPT];
__device__ float  g_sum_eu[BATCH];
__device__ float  g_sum_ev[BATCH];
__device__ float  g_tkv[BATCH * NPT * TK];
__device__ float2 g_tkpos[BATCH * NPT * TK];
__device__ float2 g_disp[BATCH * TK * NPT];            // [B][K][N] layout
__device__ float  g_geo[BATCH * TK * NPT];             // [B][K][N] layout
__device__ double g_aff[BATCH * 12];

// ---------------- feature row norms ----------------
__global__ void k_norm(const float* __restrict__ A, const float* __restrict__ Bf) {
    int warp = (blockIdx.x * blockDim.x + threadIdx.x) >> 5;
    int lane = threadIdx.x & 31;
    if (warp >= 2 * BATCH * NPT) return;
    const float* src = (warp < BATCH * NPT)
        ? A + (size_t)warp * CH
        : Bf + (size_t)(warp - BATCH * NPT) * CH;
    float s = 0.f;
#pragma unroll
    for (int t = 0; t < 4; t++) { float v = src[lane + t * 32]; s += v * v; }
#pragma unroll
    for (int off = 16; off; off >>= 1) s += __shfl_down_sync(FULLMASK, s, off);
    if (lane == 0) {
        float inv = 1.0f / fmaxf(sqrtf(s), 1e-12f);
        if (warp < BATCH * NPT) g_invA[warp] = inv;
        else                    g_invB[warp - BATCH * NPT] = inv;
    }
}

// ---------------- init sinkhorn state ----------------
__global__ void k_init() {
    int b = blockIdx.x;
    for (int j = threadIdx.x; j < NPT; j += blockDim.x) g_ev[b * NP1 + j] = 1.0f;
    if (threadIdx.x == 0) {
        g_ev[b * NP1 + NPT] = 1.0f;
        g_sum_ev[b] = (float)NPT;
        for (int s = 0; s < 12; s++) g_aff[b * 12 + s] = 0.0;
    }
}

// ---------------- fused GEMM + exp:  E = exp(nA . nB / temp) ----------------
#define BM 128
#define BN 128
#define BK 16
__global__ __launch_bounds__(256) void k_gemm_exp(
    const float* __restrict__ A, const float* __restrict__ Bf,
    const float* __restrict__ tempp)
{
    int b  = blockIdx.z;
    int bm = blockIdx.y * BM;
    int bn = blockIdx.x * BN;
    const float* Ab = A  + (size_t)b * NPT * CH;
    const float* Bb = Bf + (size_t)b * NPT * CH;
    __shared__ float As[BK][BM + 4];
    __shared__ float Bs[BK][BN + 4];
    float acc[8][8];
#pragma unroll
    for (int m = 0; m < 8; m++)
#pragma unroll
        for (int n = 0; n < 8; n++) acc[m][n] = 0.f;

    int tid = threadIdx.x;
    int lr  = tid >> 2;            // 0..63
    int lc  = (tid & 3) * 4;       // 0,4,8,12
    int ty  = tid >> 4;            // 0..15
    int tx  = tid & 15;            // 0..15

    for (int kt = 0; kt < CH; kt += BK) {
#pragma unroll
        for (int rr = 0; rr < 2; rr++) {
            int row = lr + rr * 64;
            float4 va = *(const float4*)(Ab + (size_t)(bm + row) * CH + kt + lc);
            As[lc + 0][row] = va.x; As[lc + 1][row] = va.y;
            As[lc + 2][row] = va.z; As[lc + 3][row] = va.w;
            float4 vb = *(const float4*)(Bb + (size_t)(bn + row) * CH + kt + lc);
            Bs[lc + 0][row] = vb.x; Bs[lc + 1][row] = vb.y;
            Bs[lc + 2][row] = vb.z; Bs[lc + 3][row] = vb.w;
        }
        __syncthreads();
#pragma unroll
        for (int kk = 0; kk < BK; kk++) {
            float ra[8], rb[8];
#pragma unroll
            for (int m = 0; m < 8; m++) ra[m] = As[kk][ty * 8 + m];
#pragma unroll
            for (int n = 0; n < 8; n++) rb[n] = Bs[kk][tx * 8 + n];
#pragma unroll
            for (int m = 0; m < 8; m++)
#pragma unroll
                for (int n = 0; n < 8; n++) acc[m][n] += ra[m] * rb[n];
        }
        __syncthreads();
    }

    float it = 1.0f / tempp[0];
    float ia[8], ib[8];
#pragma unroll
    for (int m = 0; m < 8; m++) ia[m] = g_invA[b * NPT + bm + ty * 8 + m] * it;
#pragma unroll
    for (int n = 0; n < 8; n++) ib[n] = g_invB[b * NPT + bn + tx * 8 + n];

#pragma unroll
    for (int m = 0; m < 8; m++) {
        float* Ep = g_E + (size_t)b * NPT * NPT + (size_t)(bm + ty * 8 + m) * NPT
                        + bn + tx * 8;
        float4 o0, o1;
        o0.x = __expf(acc[m][0] * ia[m] * ib[0]);
        o0.y = __expf(acc[m][1] * ia[m] * ib[1]);
        o0.z = __expf(acc[m][2] * ia[m] * ib[2]);
        o0.w = __expf(acc[m][3] * ia[m] * ib[3]);
        o1.x = __expf(acc[m][4] * ia[m] * ib[4]);
        o1.y = __expf(acc[m][5] * ia[m] * ib[5]);
        o1.z = __expf(acc[m][6] * ia[m] * ib[6]);
        o1.w = __expf(acc[m][7] * ia[m] * ib[7]);
        *(float4*)Ep       = o0;
        *(float4*)(Ep + 4) = o1;
    }
}

// ---------------- sinkhorn: per-iteration prologue ----------------
// zero colsum; dustbin-row u-update (uses OLD ev / sum_ev); reset accumulators
__global__ void k_pre(const float* __restrict__ dustp) {
    int b = blockIdx.x;
    for (int j = threadIdx.x; j < NPT; j += blockDim.x) g_colsum[b * NPT + j] = 0.0f;
    if (threadIdx.x == 0) {
        float db_e = __expf(dustp[0]);
        // u[N] = log_mu[N] - log(db_e*sum_ev + ev[N]);  exp(log_mu[N]) = M/(M+N) = 0.5
        float S = db_e * g_sum_ev[b] + g_ev[b * NP1 + NPT];
        g_eu[b * NP1 + NPT] = 0.5f / S;
        g_sum_eu[b] = 0.0f;
        g_sum_ev[b] = 0.0f;
    }
}

// ---------------- sinkhorn: fused row pass ----------------
// For rows i<N: S = E[i,:].ev + db_e*ev[N]; eu[i] = (1/8192)/S;
// colsum[:] += E[i,:]*eu[i]  (single streaming pass over E, row re-read hits L1)
#define ROWS_PB 16
__global__ __launch_bounds__(256) void k_row(const float* __restrict__ dustp) {
    __shared__ float ev_s[NPT];
    __shared__ float cp_s[NPT];
    __shared__ float warp_eu[8];
    int b     = blockIdx.y;
    int rbase = blockIdx.x * ROWS_PB;
    int tid = threadIdx.x, lane = tid & 31, wp = tid >> 5;
    const float* evb = g_ev + b * NP1;
    for (int j = tid; j < NPT; j += 256) { ev_s[j] = evb[j]; cp_s[j] = 0.0f; }
    __syncthreads();
    float db_e = __expf(dustp[0]);
    float evN  = evb[NPT];
    float eusum = 0.f;
    const float* Eb = g_E + (size_t)b * NPT * NPT;
#pragma unroll
    for (int r = 0; r < ROWS_PB / 8; r++) {
        int i = rbase + wp + r * 8;
        const float* Er = Eb + (size_t)i * NPT;
        float s0 = 0.f, s1 = 0.f, s2 = 0.f, s3 = 0.f;
        for (int j = lane; j < NPT; j += 128) {
            s0 += Er[j]       * ev_s[j];
            s1 += Er[j + 32]  * ev_s[j + 32];
            s2 += Er[j + 64]  * ev_s[j + 64];
            s3 += Er[j + 96]  * ev_s[j + 96];
        }
        float s = (s0 + s1) + (s2 + s3);
#pragma unroll
        for (int off = 16; off; off >>= 1) s += __shfl_down_sync(FULLMASK, s, off);
        s = __shfl_sync(FULLMASK, s, 0);
        float S   = s + db_e * evN;
        float eui = (1.0f / 8192.0f) / S;       // exp(-log(M+N))/S
        if (lane == 0) { g_eu[b * NP1 + i] = eui; eusum += eui; }
        for (int j = lane; j < NPT; j += 32)
            atomicAdd(&cp_s[j], Er[j] * eui);
    }
    if (lane == 0) warp_eu[wp] = eusum;
    __syncthreads();
    for (int j = tid; j < NPT; j += 256)
        atomicAdd(&g_colsum[b * NPT + j], cp_s[j]);
    if (tid == 0) {
        float t = 0.f;
#pragma unroll
        for (int w = 0; w < 8; w++) t += warp_eu[w];
        atomicAdd(&g_sum_eu[b], t);
    }
}

// ---------------- sinkhorn: v-update finalize ----------------
__global__ void k_vfin(const float* __restrict__ dustp) {
    int b = blockIdx.y;
    int j = blockIdx.x * 256 + threadIdx.x;
    float db_e = __expf(dustp[0]);
    float euN  = g_eu[b * NP1 + NPT];
    float S    = g_colsum[b * NPT + j] + db_e * euN;
    float evj  = (1.0f / 8192.0f) / S;
    g_ev[b * NP1 + j] = evj;
    __shared__ float red[256];
    red[threadIdx.x] = evj;
    __syncthreads();
    for (int st = 128; st; st >>= 1) {
        if (threadIdx.x < st) red[threadIdx.x] += red[threadIdx.x + st];
        __syncthreads();
    }
    if (threadIdx.x == 0) atomicAdd(&g_sum_ev[b], red[0]);
    if (blockIdx.x == 0 && threadIdx.x == 0) {
        float SN = db_e * g_sum_eu[b] + euN;     // dustbin column
        g_ev[b * NP1 + NPT] = 0.5f / SN;         // exp(log_nu[N]) = 0.5
    }
}

// ---------------- top-8 per row + gather + disp ----------------
__global__ __launch_bounds__(256) void k_topk(const float* __restrict__ posA,
                                              const float* __restrict__ posB) {
    __shared__ float ev_s[NPT];
    int tid = threadIdx.x, lane = tid & 31, wp = tid >> 5;
    int row = blockIdx.x * 8 + wp;               // 8 rows/block, same batch
    int b = row >> 12;
    int i = row & (NPT - 1);
    const float* evb = g_ev + b * NP1;
    for (int j = tid; j < NPT; j += 256) ev_s[j] = evb[j];
    __syncthreads();

    const float* Er = g_E + (size_t)b * NPT * NPT + (size_t)i * NPT;
    float tv[8]; int tj[8];
#pragma unroll
    for (int k = 0; k < 8; k++) { tv[k] = -1e30f; tj[k] = 0x7fffffff; }

    for (int j = lane; j < NPT; j += 32) {
        float p = Er[j] * ev_s[j];
        if (p > tv[7]) {
            tv[7] = p; tj[7] = j;
#pragma unroll
            for (int k = 7; k > 0; k--) {
                if (tv[k] > tv[k - 1]) {
                    float a = tv[k]; tv[k] = tv[k - 1]; tv[k - 1] = a;
                    int   c = tj[k]; tj[k] = tj[k - 1]; tj[k - 1] = c;
                }
            }
        }
    }

    float eui = g_eu[b * NP1 + i];
    float2 pa = ((const float2*)posA)[b * NPT + i];

#pragma unroll
    for (int k = 0; k < 8; k++) {
        float bv = tv[0]; int bj = tj[0];
#pragma unroll
        for (int off = 16; off; off >>= 1) {
            float ov = __shfl_down_sync(FULLMASK, bv, off);
            int   oj = __shfl_down_sync(FULLMASK, bj, off);
            if (ov > bv || (ov == bv && (unsigned)oj < (unsigned)bj)) { bv = ov; bj = oj; }
        }
        bv = __shfl_sync(FULLMASK, bv, 0);
        bj = __shfl_sync(FULLMASK, bj, 0);
        if (tv[0] == bv && tj[0] == bj) {        // unique owner (j unique per lane)
#pragma unroll
            for (int q = 0; q < 7; q++) { tv[q] = tv[q + 1]; tj[q] = tj[q + 1]; }
            tv[7] = -1e30f; tj[7] = 0x7fffffff;
        }
        if (lane == 0) {
            g_tkv[row * TK + k] = bv * eui;      // true ot_prob value
            float2 pb = ((const float2*)posB)[b * NPT + bj];
            g_tkpos[row * TK + k] = pb;
            float2 d; d.x = pb.x - pa.x; d.y = pb.y - pa.y;
            g_disp[(b * TK + k) * NPT + i] = d;
        }
    }
}

// ---------------- geometric validation (7x7 box stats, exclude-pad count) ----------------
__global__ void k_geo() {
    int t = blockIdx.x * 256 + threadIdx.x;      // [B][K][N]
    int n = t & (NPT - 1);
    int k = (t >> 12) & 7;
    int b = t >> 15;
    int h = n >> 6, w = n & 63;
    int y0 = max(h - 3, 0), y1 = min(h + 3, HH - 1);
    int x0 = max(w - 3, 0), x1 = min(w + 3, WW - 1);
    const float2* dp = g_disp + (b * TK + k) * NPT;
    float sx = 0.f, sy = 0.f, sxx = 0.f, syy = 0.f;
    for (int y = y0; y <= y1; y++)
        for (int x = x0; x <= x1; x++) {
            float2 d = dp[y * WW + x];
            sx += d.x; sy += d.y; sxx += d.x * d.x; syy += d.y * d.y;
        }
    float inv = 1.0f / (float)((y1 - y0 + 1) * (x1 - x0 + 1));
    float mx = sx * inv, my = sy * inv;
    float vx = fmaxf(sxx * inv - mx * mx, 0.f);
    float vy = fmaxf(syy * inv - my * my, 0.f);
    g_geo[t] = 1.0f / (1.0f + 100.0f * (vx + vy));
}

// ---------------- softmax refine + output + affine accumulation ----------------
__global__ __launch_bounds__(256) void k_refine(const float* __restrict__ posA,
                                                const float* __restrict__ geow,
                                                const float* __restrict__ tempp,
                                                float* __restrict__ out) {
    int t = blockIdx.x * 256 + threadIdx.x;      // t = b*N + n (block uniform b)
    int b = t >> 12;
    int n = t & (NPT - 1);
    float gw = fminf(fmaxf(geow[0], 0.f), 2.f);
    float it = 1.0f / tempp[0];

    float vals[8], cmb[8];
    float m = -1e30f;
#pragma unroll
    for (int k = 0; k < 8; k++) {
        vals[k] = g_tkv[t * TK + k];
        float g = g_geo[(b * TK + k) * NPT + n];
        cmb[k] = vals[k] + gw * g;
        m = fmaxf(m, cmb[k]);
    }
    float e[8], se = 0.f;
#pragma unroll
    for (int k = 0; k < 8; k++) { e[k] = __expf((cmb[k] - m) * it); se += e[k]; }
    float inv = 1.0f / se;
    float rx = 0.f, ry = 0.f, conf = 0.f;
#pragma unroll
    for (int k = 0; k < 8; k++) {
        float s = e[k] * inv;
        float2 p = g_tkpos[t * TK + k];
        rx += s * p.x; ry += s * p.y; conf += s * vals[k];
    }
    out[t * 2 + 0] = rx;
    out[t * 2 + 1] = ry;
    out[BATCH * NPT * 2 + t] = conf;

    // weighted-affine sums: [w, wx, wy, wxx, wxy, wyy, wxdx, wydx, wdx, wxdy, wydy, wdy]
    float2 pa = ((const float2*)posA)[t];
    float x = pa.x, y = pa.y, w = conf;
    float vv[12];
    vv[0] = w;          vv[1] = w * x;      vv[2] = w * y;
    vv[3] = w * x * x;  vv[4] = w * x * y;  vv[5] = w * y * y;
    vv[6] = w * x * rx; vv[7] = w * y * rx; vv[8] = w * rx;
    vv[9] = w * x * ry; vv[10] = w * y * ry; vv[11] = w * ry;
#pragma unroll
    for (int s = 0; s < 12; s++)
#pragma unroll
        for (int off = 16; off; off >>= 1)
            vv[s] += __shfl_down_sync(FULLMASK, vv[s], off);
    __shared__ float red[12][8];
    int lane = threadIdx.x & 31, wp = threadIdx.x >> 5;
    if (lane == 0) {
#pragma unroll
        for (int s = 0; s < 12; s++) red[s][wp] = vv[s];
    }
    __syncthreads();
    if (threadIdx.x < 12) {
        float tt = 0.f;
#pragma unroll
        for (int q = 0; q < 8; q++) tt += red[threadIdx.x][q];
        atomicAdd(&g_aff[b * 12 + threadIdx.x], (double)tt);
    }
}

// ---------------- weighted affine solve (block-diagonal -> two 3x3 Cramer) ----------------
__global__ void k_solve(float* __restrict__ out) {
    int b = threadIdx.x;
    if (b >= BATCH) return;
    const double* a = g_aff + b * 12;
    double inv = 1.0 / fmax(a[0], 1e-6);
    double m00 = a[3] * inv + 1e-4, m01 = a[4] * inv,        m02 = a[1] * inv;
    double m11 = a[5] * inv + 1e-4, m12 = a[2] * inv;
    double m22 = a[0] * inv + 1e-4;
    double rx0 = a[6] * inv, rx1 = a[7] * inv,  rx2 = a[8] * inv;
    double ry0 = a[9] * inv, ry1 = a[10] * inv, ry2 = a[11] * inv;

    double c00 = m11 * m22 - m12 * m12;
    double c01 = m02 * m12 - m01 * m22;
    double c02 = m01 * m12 - m02 * m11;
    double det = m00 * c00 + m01 * c01 + m02 * c02;
    double id  = 1.0 / det;
    double i00 = c00 * id, i01 = c01 * id, i02 = c02 * id;
    double i11 = (m00 * m22 - m02 * m02) * id;
    double i12 = (m01 * m02 - m00 * m12) * id;
    double i22 = (m00 * m11 - m01 * m01) * id;

    double A_ = i00 * rx0 + i01 * rx1 + i02 * rx2;
    double B_ = i01 * rx0 + i11 * rx1 + i12 * rx2;
    double C_ = i02 * rx0 + i12 * rx1 + i22 * rx2;
    double D_ = i00 * ry0 + i01 * ry1 + i02 * ry2;
    double E_ = i01 * ry0 + i11 * ry1 + i12 * ry2;
    double F_ = i02 * ry0 + i12 * ry1 + i22 * ry2;

    float* Hm = out + BATCH * NPT * 3 + b * 9;
    Hm[0] = (float)A_; Hm[1] = (float)B_; Hm[2] = (float)C_;
    Hm[3] = (float)D_; Hm[4] = (float)E_; Hm[5] = (float)F_;
    Hm[6] = 0.f; Hm[7] = 0.f; Hm[8] = 1.f;
}

// ---------------- launch ----------------
extern "C" void kernel_launch(void* const* d_in, const int* in_sizes, int n_in,
                              void* d_out, int out_size) {
    const float* featA = (const float*)d_in[0];
    const float* featB = (const float*)d_in[1];
    const float* posA  = (const float*)d_in[2];
    const float* posB  = (const float*)d_in[3];
    const float* dust  = (const float*)d_in[4];
    const float* geow  = (const float*)d_in[5];
    const float* temp  = (const float*)d_in[6];
    float* out = (float*)d_out;

    k_norm<<<2048, 256>>>(featA, featB);
    k_init<<<BATCH, 256>>>();

    dim3 gg(NPT / BN, NPT / BM, BATCH);
    k_gemm_exp<<<gg, 256>>>(featA, featB, temp);

    for (int itn = 0; itn < 5; itn++) {
        k_pre<<<BATCH, 256>>>(dust);
        k_row<<<dim3(NPT / ROWS_PB, BATCH), 256>>>(dust);
        k_vfin<<<dim3(NPT / 256, BATCH), 256>>>(dust);
    }

    k_topk<<<BATCH * NPT / 8, 256>>>(posA, posB);
    k_geo<<<BATCH * TK * NPT / 256, 256>>>();
    k_refine<<<BATCH * NPT / 256, 256>>>(posA, geow, temp, out);
    k_solve<<<1, 32>>>(out);
}

// round 9
// speedup vs baseline: 1.5057x; 1.5057x over previous
#include <cuda_runtime.h>
#include <math.h>

// Problem constants (fixed shapes from setup_inputs)
#define BATCH 2
#define NPT   4096      // N = H*W
#define CH    128       // feature channels
#define TK    8         // top-k
#define HH    64
#define WW    64
#define FULLMASK 0xffffffffu

typedef unsigned long long u64;

__device__ __forceinline__ u64 pack2(float lo, float hi) {
    u64 r; asm("mov.b64 %0, {%1, %2};" : "=l"(r) : "f"(lo), "f"(hi)); return r;
}
__device__ __forceinline__ void fma2(u64& d, u64 a, u64 b) {
    asm("fma.rn.f32x2 %0, %1, %2, %0;" : "+l"(d) : "l"(a), "l"(b));
}
__device__ __forceinline__ float2 unpack2(u64 v) {
    float2 r; asm("mov.b64 {%0, %1}, %2;" : "=f"(r.x), "=f"(r.y) : "l"(v)); return r;
}

// ---------------- device scratch (static allocation only) ----------------
// NOTE: ev/eu split into stride-NPT vector part (16B-aligned for float4) +
// scalar dustbin entries. (R8 fault: b*4097 float offset broke LDG.128.)
__device__ float  g_invA[BATCH * NPT];
__device__ float  g_invB[BATCH * NPT];
__device__ float  g_E[(size_t)BATCH * NPT * NPT];      // exp(scores), 134 MB
__device__ float  g_eu[BATCH * NPT];
__device__ float  g_ev[BATCH * NPT];
__device__ float  g_euN[BATCH];                        // dustbin row
__device__ float  g_evN[BATCH];                        // dustbin col
__device__ float  g_colsum[BATCH * NPT];
__device__ float  g_sum_eu[BATCH];
__device__ float  g_sum_ev[BATCH];
__device__ float  g_tkv[BATCH * NPT * TK];
__device__ float2 g_tkpos[BATCH * NPT * TK];
__device__ float2 g_disp[BATCH * TK * NPT];            // [B][K][N] layout
__device__ float  g_geo[BATCH * TK * NPT];             // [B][K][N] layout
__device__ double g_aff[BATCH * 12];

// ---------------- feature row norms ----------------
__global__ void k_norm(const float* __restrict__ A, const float* __restrict__ Bf) {
    int warp = (blockIdx.x * blockDim.x + threadIdx.x) >> 5;
    int lane = threadIdx.x & 31;
    if (warp >= 2 * BATCH * NPT) return;
    const float* src = (warp < BATCH * NPT)
        ? A + (size_t)warp * CH
        : Bf + (size_t)(warp - BATCH * NPT) * CH;
    float s = 0.f;
#pragma unroll
    for (int t = 0; t < 4; t++) { float v = src[lane + t * 32]; s += v * v; }
#pragma unroll
    for (int off = 16; off; off >>= 1) s += __shfl_down_sync(FULLMASK, s, off);
    if (lane == 0) {
        float inv = 1.0f / fmaxf(sqrtf(s), 1e-12f);
        if (warp < BATCH * NPT) g_invA[warp] = inv;
        else                    g_invB[warp - BATCH * NPT] = inv;
    }
}

// ---------------- init sinkhorn state ----------------
__global__ void k_init() {
    int b = blockIdx.x;
    for (int j = threadIdx.x; j < NPT; j += blockDim.x) {
        g_ev[b * NPT + j] = 1.0f;
        g_colsum[b * NPT + j] = 0.0f;
    }
    if (threadIdx.x == 0) {
        g_evN[b] = 1.0f;
        g_sum_ev[b] = (float)NPT;
        g_sum_eu[b] = 0.0f;
        for (int s = 0; s < 12; s++) g_aff[b * 12 + s] = 0.0;
    }
}

// ---------------- fused GEMM + exp via packed f32x2 ----------------
#define BM 128
#define BN 128
#define BK 16
__global__ __launch_bounds__(256) void k_gemm_exp(
    const float* __restrict__ A, const float* __restrict__ Bf,
    const float* __restrict__ tempp)
{
    int b  = blockIdx.z;
    int bm = blockIdx.y * BM;
    int bn = blockIdx.x * BN;
    const float* Ab = A  + (size_t)b * NPT * CH;
    const float* Bb = Bf + (size_t)b * NPT * CH;
    __shared__ __align__(16) float As[BK][BM + 4];
    __shared__ __align__(16) float Bs[BK][BN + 4];
    u64 acc[8][4];
#pragma unroll
    for (int m = 0; m < 8; m++)
#pragma unroll
        for (int p = 0; p < 4; p++) acc[m][p] = 0ull;

    int tid = threadIdx.x;
    int lr  = tid >> 2;            // 0..63
    int lc  = (tid & 3) * 4;       // 0,4,8,12
    int ty  = tid >> 4;            // 0..15
    int tx  = tid & 15;            // 0..15

    for (int kt = 0; kt < CH; kt += BK) {
#pragma unroll
        for (int rr = 0; rr < 2; rr++) {
            int row = lr + rr * 64;
            float4 va = *(const float4*)(Ab + (size_t)(bm + row) * CH + kt + lc);
            As[lc + 0][row] = va.x; As[lc + 1][row] = va.y;
            As[lc + 2][row] = va.z; As[lc + 3][row] = va.w;
            float4 vb = *(const float4*)(Bb + (size_t)(bn + row) * CH + kt + lc);
            Bs[lc + 0][row] = vb.x; Bs[lc + 1][row] = vb.y;
            Bs[lc + 2][row] = vb.z; Bs[lc + 3][row] = vb.w;
        }
        __syncthreads();
#pragma unroll
        for (int kk = 0; kk < BK; kk++) {
            float4 a0 = *(const float4*)&As[kk][ty * 8];
            float4 a1 = *(const float4*)&As[kk][ty * 8 + 4];
            float4 b0 = *(const float4*)&Bs[kk][tx * 8];
            float4 b1 = *(const float4*)&Bs[kk][tx * 8 + 4];
            u64 bp[4];
            bp[0] = pack2(b0.x, b0.y); bp[1] = pack2(b0.z, b0.w);
            bp[2] = pack2(b1.x, b1.y); bp[3] = pack2(b1.z, b1.w);
            float am[8] = {a0.x, a0.y, a0.z, a0.w, a1.x, a1.y, a1.z, a1.w};
#pragma unroll
            for (int m = 0; m < 8; m++) {
                u64 ad = pack2(am[m], am[m]);
#pragma unroll
                for (int p = 0; p < 4; p++) fma2(acc[m][p], ad, bp[p]);
            }
        }
        __syncthreads();
    }

    float it = 1.0f / tempp[0];
    float ia[8], ib[8];
#pragma unroll
    for (int m = 0; m < 8; m++) ia[m] = g_invA[b * NPT + bm + ty * 8 + m] * it;
#pragma unroll
    for (int n = 0; n < 8; n++) ib[n] = g_invB[b * NPT + bn + tx * 8 + n];

#pragma unroll
    for (int m = 0; m < 8; m++) {
        float* Ep = g_E + (size_t)b * NPT * NPT + (size_t)(bm + ty * 8 + m) * NPT
                        + bn + tx * 8;
        float2 v0 = unpack2(acc[m][0]);
        float2 v1 = unpack2(acc[m][1]);
        float2 v2 = unpack2(acc[m][2]);
        float2 v3 = unpack2(acc[m][3]);
        float4 o0, o1;
        o0.x = __expf(v0.x * ia[m] * ib[0]);
        o0.y = __expf(v0.y * ia[m] * ib[1]);
        o0.z = __expf(v1.x * ia[m] * ib[2]);
        o0.w = __expf(v1.y * ia[m] * ib[3]);
        o1.x = __expf(v2.x * ia[m] * ib[4]);
        o1.y = __expf(v2.y * ia[m] * ib[5]);
        o1.z = __expf(v3.x * ia[m] * ib[6]);
        o1.w = __expf(v3.y * ia[m] * ib[7]);
        *(float4*)Ep       = o0;
        *(float4*)(Ep + 4) = o1;
    }
}

// ---------------- sinkhorn: fused row pass (two-phase, no shared atomics) ----------------
// Phase 1: each warp computes 2 row-dots S = E[i,:].ev + db_e*evN -> eu[i]
// Phase 2: each warp owns a 512-column slice; accumulates colsum in registers
//          over the block's 16 rows (tile re-read hits L1/L2), then red.global.
// Block (0,b) also computes this iteration's dustbin-row eu and resets sum_ev.
#define ROWS_PB 16
__global__ __launch_bounds__(256) void k_row(const float* __restrict__ dustp) {
    __shared__ __align__(16) float ev_s[NPT];
    __shared__ float eu_s[ROWS_PB];
    __shared__ float warp_eu[8];
    int b     = blockIdx.y;
    int rbase = blockIdx.x * ROWS_PB;
    int tid = threadIdx.x, lane = tid & 31, wp = tid >> 5;
    const float* evb = g_ev + b * NPT;           // 16B-aligned (stride NPT)
    float4* ev4s = (float4*)ev_s;
    const float4* ev4g = (const float4*)evb;
    for (int j = tid; j < NPT / 4; j += 256) ev4s[j] = ev4g[j];
    float db_e = __expf(dustp[0]);
    float evN  = g_evN[b];
    if (blockIdx.x == 0 && tid == 0) {
        // dustbin-row u-update for THIS iteration (uses prev sum_ev / evN)
        float S = db_e * g_sum_ev[b] + evN;
        g_euN[b] = 0.5f / S;
        g_sum_ev[b] = 0.0f;
    }
    __syncthreads();

    const float* Eb = g_E + (size_t)b * NPT * NPT;
    float eusum = 0.f;
#pragma unroll
    for (int r = wp; r < ROWS_PB; r += 8) {
        int i = rbase + r;
        const float4* Er4 = (const float4*)(Eb + (size_t)i * NPT);
        float s0 = 0.f, s1 = 0.f;
        for (int j = lane; j < NPT / 4; j += 64) {
            float4 e = Er4[j];      float4 v = ev4s[j];
            s0 += e.x * v.x + e.y * v.y + e.z * v.z + e.w * v.w;
            float4 e2 = Er4[j + 32]; float4 v2 = ev4s[j + 32];
            s1 += e2.x * v2.x + e2.y * v2.y + e2.z * v2.z + e2.w * v2.w;
        }
        float s = s0 + s1;
#pragma unroll
        for (int off = 16; off; off >>= 1) s += __shfl_down_sync(FULLMASK, s, off);
        if (lane == 0) {
            float eui = (1.0f / 8192.0f) / (s + db_e * evN);
            g_eu[b * NPT + i] = eui;
            eu_s[r] = eui;
            eusum += eui;
        }
    }
    if (lane == 0) warp_eu[wp] = eusum;
    __syncthreads();
    if (tid == 0) {
        float t = 0.f;
#pragma unroll
        for (int w = 0; w < 8; w++) t += warp_eu[w];
        atomicAdd(&g_sum_eu[b], t);
    }

    // phase 2: warp wp owns float4-columns [wp*128, wp*128+128)
    float4 a0 = make_float4(0, 0, 0, 0), a1 = a0, a2 = a0, a3 = a0;
    int fb = wp * 128 + lane;
#pragma unroll 4
    for (int r = 0; r < ROWS_PB; r++) {
        const float4* Er4 = (const float4*)(Eb + (size_t)(rbase + r) * NPT);
        float w = eu_s[r];
        float4 e0 = Er4[fb];      float4 e1 = Er4[fb + 32];
        float4 e2 = Er4[fb + 64]; float4 e3 = Er4[fb + 96];
        a0.x += e0.x * w; a0.y += e0.y * w; a0.z += e0.z * w; a0.w += e0.w * w;
        a1.x += e1.x * w; a1.y += e1.y * w; a1.z += e1.z * w; a1.w += e1.w * w;
        a2.x += e2.x * w; a2.y += e2.y * w; a2.z += e2.z * w; a2.w += e2.w * w;
        a3.x += e3.x * w; a3.y += e3.y * w; a3.z += e3.z * w; a3.w += e3.w * w;
    }
    float* cs = g_colsum + b * NPT;
    atomicAdd(&cs[4 * fb + 0],        a0.x); atomicAdd(&cs[4 * fb + 1],        a0.y);
    atomicAdd(&cs[4 * fb + 2],        a0.z); atomicAdd(&cs[4 * fb + 3],        a0.w);
    atomicAdd(&cs[4 * (fb + 32) + 0], a1.x); atomicAdd(&cs[4 * (fb + 32) + 1], a1.y);
    atomicAdd(&cs[4 * (fb + 32) + 2], a1.z); atomicAdd(&cs[4 * (fb + 32) + 3], a1.w);
    atomicAdd(&cs[4 * (fb + 64) + 0], a2.x); atomicAdd(&cs[4 * (fb + 64) + 1], a2.y);
    atomicAdd(&cs[4 * (fb + 64) + 2], a2.z); atomicAdd(&cs[4 * (fb + 64) + 3], a2.w);
    atomicAdd(&cs[4 * (fb + 96) + 0], a3.x); atomicAdd(&cs[4 * (fb + 96) + 1], a3.y);
    atomicAdd(&cs[4 * (fb + 96) + 2], a3.z); atomicAdd(&cs[4 * (fb + 96) + 3], a3.w);
}

// ---------------- sinkhorn: v-update finalize (+ prologue for next iter) ----------------
__global__ void k_vfin(const float* __restrict__ dustp) {
    int b = blockIdx.y;
    int j = blockIdx.x * 256 + threadIdx.x;
    float db_e = __expf(dustp[0]);
    float euN  = g_euN[b];
    float S    = g_colsum[b * NPT + j] + db_e * euN;
    float evj  = (1.0f / 8192.0f) / S;
    g_ev[b * NPT + j] = evj;
    g_colsum[b * NPT + j] = 0.0f;            // ready for next iteration
    __shared__ float red[256];
    red[threadIdx.x] = evj;
    __syncthreads();
    for (int st = 128; st; st >>= 1) {
        if (threadIdx.x < st) red[threadIdx.x] += red[threadIdx.x + st];
        __syncthreads();
    }
    if (threadIdx.x == 0) atomicAdd(&g_sum_ev[b], red[0]);
    if (blockIdx.x == 0 && threadIdx.x == 0) {
        float SN = db_e * g_sum_eu[b] + euN;  // dustbin column
        g_evN[b] = 0.5f / SN;
        g_sum_eu[b] = 0.0f;                   // ready for next iteration
    }
}

// ---------------- top-8 per row + gather + disp ----------------
__global__ __launch_bounds__(256) void k_topk(const float* __restrict__ posA,
                                              const float* __restrict__ posB) {
    __shared__ __align__(16) float ev_s[NPT];
    int tid = threadIdx.x, lane = tid & 31, wp = tid >> 5;
    int row = blockIdx.x * 8 + wp;               // 8 rows/block, same batch
    int b = row >> 12;
    int i = row & (NPT - 1);
    float4* ev4s = (float4*)ev_s;
    const float4* ev4g = (const float4*)(g_ev + b * NPT);   // 16B-aligned
    for (int j = tid; j < NPT / 4; j += 256) ev4s[j] = ev4g[j];
    __syncthreads();

    const float4* Er4 = (const float4*)(g_E + (size_t)b * NPT * NPT + (size_t)i * NPT);
    float tv[8]; int tj[8];
#pragma unroll
    for (int k = 0; k < 8; k++) { tv[k] = -1e30f; tj[k] = 0x7fffffff; }

    for (int j4 = lane; j4 < NPT / 4; j4 += 32) {
        float4 e = Er4[j4];
        float4 v = ev4s[j4];
        float p[4] = { e.x * v.x, e.y * v.y, e.z * v.z, e.w * v.w };
#pragma unroll
        for (int c = 0; c < 4; c++) {
            if (p[c] > tv[7]) {
                tv[7] = p[c]; tj[7] = j4 * 4 + c;
#pragma unroll
                for (int k = 7; k > 0; k--) {
                    if (tv[k] > tv[k - 1]) {
                        float a = tv[k]; tv[k] = tv[k - 1]; tv[k - 1] = a;
                        int   q = tj[k]; tj[k] = tj[k - 1]; tj[k - 1] = q;
                    }
                }
            }
        }
    }

    float eui = g_eu[b * NPT + i];
    float2 pa = ((const float2*)posA)[b * NPT + i];

#pragma unroll
    for (int k = 0; k < 8; k++) {
        float bv = tv[0]; int bj = tj[0];
#pragma unroll
        for (int off = 16; off; off >>= 1) {
            float ov = __shfl_down_sync(FULLMASK, bv, off);
            int   oj = __shfl_down_sync(FULLMASK, bj, off);
            if (ov > bv || (ov == bv && (unsigned)oj < (unsigned)bj)) { bv = ov; bj = oj; }
        }
        bv = __shfl_sync(FULLMASK, bv, 0);
        bj = __shfl_sync(FULLMASK, bj, 0);
        if (tv[0] == bv && tj[0] == bj) {        // unique owner (j unique per lane)
#pragma unroll
            for (int q = 0; q < 7; q++) { tv[q] = tv[q + 1]; tj[q] = tj[q + 1]; }
            tv[7] = -1e30f; tj[7] = 0x7fffffff;
        }
        if (lane == 0) {
            g_tkv[row * TK + k] = bv * eui;      // true ot_prob value
            float2 pb = ((const float2*)posB)[b * NPT + bj];
            g_tkpos[row * TK + k] = pb;
            float2 d; d.x = pb.x - pa.x; d.y = pb.y - pa.y;
            g_disp[(b * TK + k) * NPT + i] = d;
        }
    }
}

// ---------------- geometric validation (7x7 box stats, exclude-pad count) ----------------
__global__ void k_geo() {
    int t = blockIdx.x * 256 + threadIdx.x;      // [B][K][N]
    int n = t & (NPT - 1);
    int k = (t >> 12) & 7;
    int b = t >> 15;
    int h = n >> 6, w = n & 63;
    int y0 = max(h - 3, 0), y1 = min(h + 3, HH - 1);
    int x0 = max(w - 3, 0), x1 = min(w + 3, WW - 1);
    const float2* dp = g_disp + (b * TK + k) * NPT;
    float sx = 0.f, sy = 0.f, sxx = 0.f, syy = 0.f;
    for (int y = y0; y <= y1; y++)
        for (int x = x0; x <= x1; x++) {
            float2 d = dp[y * WW + x];
            sx += d.x; sy += d.y; sxx += d.x * d.x; syy += d.y * d.y;
        }
    float inv = 1.0f / (float)((y1 - y0 + 1) * (x1 - x0 + 1));
    float mx = sx * inv, my = sy * inv;
    float vx = fmaxf(sxx * inv - mx * mx, 0.f);
    float vy = fmaxf(syy * inv - my * my, 0.f);
    g_geo[t] = 1.0f / (1.0f + 100.0f * (vx + vy));
}

// ---------------- softmax refine + output + affine accumulation ----------------
__global__ __launch_bounds__(256) void k_refine(const float* __restrict__ posA,
                                                const float* __restrict__ geow,
                                                const float* __restrict__ tempp,
                                                float* __restrict__ out) {
    int t = blockIdx.x * 256 + threadIdx.x;      // t = b*N + n (block uniform b)
    int b = t >> 12;
    int n = t & (NPT - 1);
    float gw = fminf(fmaxf(geow[0], 0.f), 2.f);
    float it = 1.0f / tempp[0];

    float vals[8], cmb[8];
    float m = -1e30f;
#pragma unroll
    for (int k = 0; k < 8; k++) {
        vals[k] = g_tkv[t * TK + k];
        float g = g_geo[(b * TK + k) * NPT + n];
        cmb[k] = vals[k] + gw * g;
        m = fmaxf(m, cmb[k]);
    }
    float e[8], se = 0.f;
#pragma unroll
    for (int k = 0; k < 8; k++) { e[k] = __expf((cmb[k] - m) * it); se += e[k]; }
    float inv = 1.0f / se;
    float rx = 0.f, ry = 0.f, conf = 0.f;
#pragma unroll
    for (int k = 0; k < 8; k++) {
        float s = e[k] * inv;
        float2 p = g_tkpos[t * TK + k];
        rx += s * p.x; ry += s * p.y; conf += s * vals[k];
    }
    out[t * 2 + 0] = rx;
    out[t * 2 + 1] = ry;
    out[BATCH * NPT * 2 + t] = conf;

    // weighted-affine sums: [w, wx, wy, wxx, wxy, wyy, wxdx, wydx, wdx, wxdy, wydy, wdy]
    float2 pa = ((const float2*)posA)[t];
    float x = pa.x, y = pa.y, w = conf;
    float vv[12];
    vv[0] = w;          vv[1] = w * x;      vv[2] = w * y;
    vv[3] = w * x * x;  vv[4] = w * x * y;  vv[5] = w * y * y;
    vv[6] = w * x * rx; vv[7] = w * y * rx; vv[8] = w * rx;
    vv[9] = w * x * ry; vv[10] = w * y * ry; vv[11] = w * ry;
#pragma unroll
    for (int s = 0; s < 12; s++)
#pragma unroll
        for (int off = 16; off; off >>= 1)
            vv[s] += __shfl_down_sync(FULLMASK, vv[s], off);
    __shared__ float red[12][8];
    int lane = threadIdx.x & 31, wp = threadIdx.x >> 5;
    if (lane == 0) {
#pragma unroll
        for (int s = 0; s < 12; s++) red[s][wp] = vv[s];
    }
    __syncthreads();
    if (threadIdx.x < 12) {
        float tt = 0.f;
#pragma unroll
        for (int q = 0; q < 8; q++) tt += red[threadIdx.x][q];
        atomicAdd(&g_aff[b * 12 + threadIdx.x], (double)tt);
    }
}

// ---------------- weighted affine solve (block-diagonal -> two 3x3 Cramer) ----------------
__global__ void k_solve(float* __restrict__ out) {
    int b = threadIdx.x;
    if (b >= BATCH) return;
    const double* a = g_aff + b * 12;
    double inv = 1.0 / fmax(a[0], 1e-6);
    double m00 = a[3] * inv + 1e-4, m01 = a[4] * inv,        m02 = a[1] * inv;
    double m11 = a[5] * inv + 1e-4, m12 = a[2] * inv;
    double m22 = a[0] * inv + 1e-4;
    double rx0 = a[6] * inv, rx1 = a[7] * inv,  rx2 = a[8] * inv;
    double ry0 = a[9] * inv, ry1 = a[10] * inv, ry2 = a[11] * inv;

    double c00 = m11 * m22 - m12 * m12;
    double c01 = m02 * m12 - m01 * m22;
    double c02 = m01 * m12 - m02 * m11;
    double det = m00 * c00 + m01 * c01 + m02 * c02;
    double id  = 1.0 / det;
    double i00 = c00 * id, i01 = c01 * id, i02 = c02 * id;
    double i11 = (m00 * m22 - m02 * m02) * id;
    double i12 = (m01 * m02 - m00 * m12) * id;
    double i22 = (m00 * m11 - m01 * m01) * id;

    double A_ = i00 * rx0 + i01 * rx1 + i02 * rx2;
    double B_ = i01 * rx0 + i11 * rx1 + i12 * rx2;
    double C_ = i02 * rx0 + i12 * rx1 + i22 * rx2;
    double D_ = i00 * ry0 + i01 * ry1 + i02 * ry2;
    double E_ = i01 * ry0 + i11 * ry1 + i12 * ry2;
    double F_ = i02 * ry0 + i12 * ry1 + i22 * ry2;

    float* Hm = out + BATCH * NPT * 3 + b * 9;
    Hm[0] = (float)A_; Hm[1] = (float)B_; Hm[2] = (float)C_;
    Hm[3] = (float)D_; Hm[4] = (float)E_; Hm[5] = (float)F_;
    Hm[6] = 0.f; Hm[7] = 0.f; Hm[8] = 1.f;
}

// ---------------- launch ----------------
extern "C" void kernel_launch(void* const* d_in, const int* in_sizes, int n_in,
                              void* d_out, int out_size) {
    const float* featA = (const float*)d_in[0];
    const float* featB = (const float*)d_in[1];
    const float* posA  = (const float*)d_in[2];
    const float* posB  = (const float*)d_in[3];
    const float* dust  = (const float*)d_in[4];
    const float* geow  = (const float*)d_in[5];
    const float* temp  = (const float*)d_in[6];
    float* out = (float*)d_out;

    k_norm<<<2048, 256>>>(featA, featB);
    k_init<<<BATCH, 256>>>();

    dim3 gg(NPT / BN, NPT / BM, BATCH);
    k_gemm_exp<<<gg, 256>>>(featA, featB, temp);

    for (int itn = 0; itn < 5; itn++) {
        k_row<<<dim3(NPT / ROWS_PB, BATCH), 256>>>(dust);
        k_vfin<<<dim3(NPT / 256, BATCH), 256>>>(dust);
    }

    k_topk<<<BATCH * NPT / 8, 256>>>(posA, posB);
    k_geo<<<BATCH * TK * NPT / 256, 256>>>();
    k_refine<<<BATCH * NPT / 256, 256>>>(posA, geow, temp, out);
    k_solve<<<1, 32>>>(out);
}